// round 16
// baseline (speedup 1.0000x reference)
#include <cuda_runtime.h>
#include <cuda_bf16.h>
#include <math.h>
#include <stdint.h>

#define NIMG   16
#define NANCH  8732
#define NCLS   80
#define FLATC  (NANCH * NCLS)     // 698560
#define NCAND  400
#define NOUT   200
#define CAP    4096
#define CLIPV  4.135166556742356f // log(1000/16)

// ---------------- device scratch (no allocations allowed) ----------------
__device__ float        g_cls[(size_t)NIMG * NANCH * 81];   // logits
__device__ float        g_scr[(size_t)NIMG * FLATC];        // thresholded softmax scores
__device__ float        g_reg[(size_t)NIMG * NANCH * 4];    // box deltas
__device__ unsigned int g_hist[NIMG * 65536];
__device__ int          g_cnt[NIMG];
__device__ unsigned int g_thr[NIMG];
__device__ float        g_cand_v[NIMG * CAP];
__device__ int          g_cand_i[NIMG * CAP];
__device__ float        g_top_v[NIMG * NCAND];
__device__ int          g_top_i[NIMG * NCAND];

// pre-split operands: (c0,c1,c2,0) ushort4 packed in one uint64 per value
__device__ unsigned long long g_wsplit[11358720];   // weights, per-level rows
__device__ unsigned long long g_fsplit[18706432];   // features, level-linear

// ---------------- zero histograms ----------------
__global__ void zero_kernel()
{
    int i  = blockIdx.x * blockDim.x + threadIdx.x;
    int st = gridDim.x * blockDim.x;
    for (int t = i; t < NIMG * 65536; t += st) g_hist[t] = 0u;
}

// ============ conv heads via warp-level HMMA (bf16 3-way split) ============
struct HeadPtrs {
    const float* feat[6];
    const float* cw[6];
    const float* cb[6];
    const float* rw[6];
    const float* rb[6];
};

__device__ __constant__ int d_C[6]    = {512, 1024, 512, 256, 256, 256};
__device__ __constant__ int d_H[6]    = {38, 19, 10, 5, 3, 1};
__device__ __constant__ int d_AN[6]   = {4, 6, 6, 6, 4, 4};
__device__ __constant__ int d_AOFF[6] = {0, 5776, 7942, 8542, 8692, 8728};
__device__ __constant__ int d_NX[6]   = {181, 46, 13, 4, 2, 1};  // ceil(Nc/128)
__device__ __constant__ int d_WB[6]   = {0, 1566720, 6266880, 8616960,
                                         9792000, 10575360};     // g_wsplit bases
__device__ __constant__ int d_FB[6]   = {0, 11829248, 17743872, 18563072,
                                         18665472, 18702336};    // g_fsplit bases
__device__ __constant__ int d_FSZ[6]  = {11829248, 5914624, 819200, 102400,
                                         36864, 4096};

#define PITCH   80                   // 64B data + 16B pad: conflict-free ldmatrix
#define CTILE   (128 * PITCH)        // one component tile: 10240 B
#define SMEM_HM (6 * CTILE)          // 61440 B (3 A comps + 3 B comps)

// 3-way bf16 split, packed (identical RN op sequence as the in-loop version
// of the round-15 kernel -> bitwise-identical components)
__device__ __forceinline__ unsigned long long split64(float x)
{
    const __nv_bfloat16 h0 = __float2bfloat16(x);
    const float r = x - __bfloat162float(h0);
    const __nv_bfloat16 h1 = __float2bfloat16(r);
    const float s = r - __bfloat162float(h1);
    const __nv_bfloat16 h2 = __float2bfloat16(s);
    return (unsigned long long)__bfloat16_as_ushort(h0)
         | ((unsigned long long)__bfloat16_as_ushort(h1) << 16)
         | ((unsigned long long)__bfloat16_as_ushort(h2) << 32);
}

// ---------------- pre-split passes (run once per launch) ----------------
__global__ void presplit_w(const HeadPtrs P)
{
    const int gid = blockIdx.x * blockDim.x + threadIdx.x;
    const int st  = gridDim.x * blockDim.x;
#pragma unroll
    for (int li = 0; li < 6; ++li) {
        const int K  = d_C[li] * 9;
        const int Mc = d_AN[li] * 81;
        const int M  = d_AN[li] * 85;
        const int total = M * K;
        const float* cw = P.cw[li];
        const float* rw = P.rw[li];
        unsigned long long* out = g_wsplit + d_WB[li];
        for (int j = gid; j < total; j += st) {
            const int m = j / K, k = j - m * K;
            const float x = (m < Mc) ? cw[(size_t)m * K + k]
                                     : rw[(size_t)(m - Mc) * K + k];
            out[j] = split64(x);
        }
    }
}

__global__ void presplit_f(const HeadPtrs P)
{
    const int gid = blockIdx.x * blockDim.x + threadIdx.x;
    const int st  = gridDim.x * blockDim.x;
#pragma unroll
    for (int li = 0; li < 6; ++li) {
        const int total = d_FSZ[li];
        const float* f = P.feat[li];
        unsigned long long* out = g_fsplit + d_FB[li];
        for (int j = gid; j < total; j += st)
            out[j] = split64(f[j]);
    }
}

__device__ __forceinline__ void ldsm4(uint32_t* r, uint32_t addr)
{
    asm volatile("ldmatrix.sync.aligned.m8n8.x4.shared.b16 {%0,%1,%2,%3}, [%4];"
                 : "=r"(r[0]), "=r"(r[1]), "=r"(r[2]), "=r"(r[3]) : "r"(addr));
}

__device__ __forceinline__ void mma16816(float* c, const uint32_t* a, const uint32_t* b)
{
    asm volatile(
        "mma.sync.aligned.m16n8k16.row.col.f32.bf16.bf16.f32 "
        "{%0,%1,%2,%3},{%4,%5,%6,%7},{%8,%9},{%0,%1,%2,%3};"
        : "+f"(c[0]), "+f"(c[1]), "+f"(c[2]), "+f"(c[3])
        : "r"(a[0]), "r"(a[1]), "r"(a[2]), "r"(a[3]), "r"(b[0]), "r"(b[1]));
}

// unpack 8 packed values (as 4 x uint2-pairs) into 3 comp uint4s and store
__device__ __forceinline__ void pack_store8(char* base, uint32_t off,
                                            const unsigned long long* v)
{
    uint32_t c0[4], c1[4], c2[4];
#pragma unroll
    for (int p = 0; p < 4; ++p) {
        const uint32_t aL = (uint32_t)v[2 * p];
        const uint32_t aH = (uint32_t)(v[2 * p] >> 32);
        const uint32_t bL = (uint32_t)v[2 * p + 1];
        const uint32_t bH = (uint32_t)(v[2 * p + 1] >> 32);
        c0[p] = __byte_perm(aL, bL, 0x5410);
        c1[p] = __byte_perm(aL, bL, 0x7632);
        c2[p] = __byte_perm(aH, bH, 0x5410);
    }
    *(uint4*)(base + off)             = make_uint4(c0[0], c0[1], c0[2], c0[3]);
    *(uint4*)(base + CTILE + off)     = make_uint4(c1[0], c1[1], c1[2], c1[3]);
    *(uint4*)(base + 2 * CTILE + off) = make_uint4(c2[0], c2[1], c2[2], c2[3]);
}

__device__ __forceinline__ void zero_store8(char* base, uint32_t off)
{
    const uint4 z = make_uint4(0, 0, 0, 0);
    *(uint4*)(base + off)             = z;
    *(uint4*)(base + CTILE + off)     = z;
    *(uint4*)(base + 2 * CTILE + off) = z;
}

__global__ void __launch_bounds__(256, 1)
head_gemm_hmma(const HeadPtrs P)
{
    // ---- block -> (level, tile) mapping; work-heavy levels first ----
    const int b = blockIdx.x;
    int li, rel;
    if      (b < 184) { li = 1; rel = b; }
    else if (b < 727) { li = 0; rel = b - 184; }
    else if (b < 779) { li = 2; rel = b - 727; }
    else if (b < 795) { li = 3; rel = b - 779; }
    else if (b < 801) { li = 4; rel = b - 795; }
    else              { li = 5; rel = b - 801; }

    const int C  = d_C[li];
    const int H  = d_H[li];
    const int W  = H;
    const int an = d_AN[li];
    const int aoff = d_AOFF[li];
    const int nx = d_NX[li];
    const int Mc = an * 81;
    const int M  = an * 85;
    const int HW = H * W;
    const int Ncols = NIMG * HW;
    const int K  = C * 9;            // 4608 / 9216 / 2304: all % 384 == 0

    const float* __restrict__ cb = P.cb[li];
    const float* __restrict__ rb = P.rb[li];

    extern __shared__ __align__(16) char dsm[];
    uint32_t sb;
    asm("{ .reg .u64 t; cvta.to.shared.u64 t, %1; cvt.u32.u64 %0, t; }"
        : "=r"(sb) : "l"(dsm));

    const int tid  = threadIdx.x;
    const int wid  = tid >> 5, lane = tid & 31;
    const int m0   = (rel / nx) * 128;
    const int n0   = (rel % nx) * 128;

    // ---- converter role: threads 0-127 -> A rows, 128-255 -> B cols ----
    const bool isA = (tid < 128);
    const int crow = isA ? tid : tid - 128;

    const unsigned long long* a64 = nullptr;
    if (isA) {
        const int am = m0 + crow;
        if (am < M) a64 = g_wsplit + d_WB[li] + (size_t)am * K;
    }
    bool colv = false;
    int img = 0, oh = 0, ow = 0;
    if (!isA) {
        const int col = n0 + crow;
        colv = (col < Ncols);
        if (colv) { img = col / HW; int r = col % HW; oh = r / W; ow = r % W; }
    }
    const unsigned long long* fimg64 =
        g_fsplit + d_FB[li] + (size_t)img * C * HW;
    const uint32_t cvt_off = (uint32_t)crow * PITCH;

    // ---- warp tile mapping: 8 warps = 2 m-halves x 4 n-quarters ----
    const int m0w = (wid >> 2) * 64;   // 0 or 64
    const int n0w = (wid & 3) * 32;    // 0,32,64,96

    const uint32_t a_off = (uint32_t)(m0w + (lane & 15)) * PITCH + (lane >> 4) * 16;
    const uint32_t b_off = (uint32_t)(n0w + (lane & 7) + ((lane >> 4) << 3)) * PITCH
                         + ((lane >> 3) & 1) * 16;

    float acc[4][4][4], hi[4][4][4];
#pragma unroll
    for (int i = 0; i < 4; ++i)
#pragma unroll
        for (int j = 0; j < 4; ++j)
#pragma unroll
            for (int u = 0; u < 4; ++u) { acc[i][j][u] = 0.f; hi[i][j][u] = 0.f; }

    const int nch = K >> 5;          // K-chunks of 32
    int fcnt = 0;

    for (int ch = 0; ch < nch; ++ch) {
        const int k0 = ch << 5;

        // ---- unpack pre-split chunk into smem component tiles ----
        if (isA) {
            if (a64) {
#pragma unroll
                for (int q = 0; q < 4; ++q) {
                    unsigned long long v[8];
                    const uint4 u0 = *(const uint4*)(a64 + k0 + q * 8);
                    const uint4 u1 = *(const uint4*)(a64 + k0 + q * 8 + 2);
                    const uint4 u2 = *(const uint4*)(a64 + k0 + q * 8 + 4);
                    const uint4 u3 = *(const uint4*)(a64 + k0 + q * 8 + 6);
                    v[0] = (unsigned long long)u0.x | ((unsigned long long)u0.y << 32);
                    v[1] = (unsigned long long)u0.z | ((unsigned long long)u0.w << 32);
                    v[2] = (unsigned long long)u1.x | ((unsigned long long)u1.y << 32);
                    v[3] = (unsigned long long)u1.z | ((unsigned long long)u1.w << 32);
                    v[4] = (unsigned long long)u2.x | ((unsigned long long)u2.y << 32);
                    v[5] = (unsigned long long)u2.z | ((unsigned long long)u2.w << 32);
                    v[6] = (unsigned long long)u3.x | ((unsigned long long)u3.y << 32);
                    v[7] = (unsigned long long)u3.z | ((unsigned long long)u3.w << 32);
                    pack_store8(dsm, cvt_off + q * 16, v);
                }
            } else if (ch == 0) {
#pragma unroll
                for (int q = 0; q < 4; ++q) zero_store8(dsm, cvt_off + q * 16);
            }
        } else {
            if (colv) {
#pragma unroll
                for (int q = 0; q < 4; ++q) {
                    unsigned long long v[8];
#pragma unroll
                    for (int u = 0; u < 8; ++u) {
                        const int k = k0 + q * 8 + u;
                        const int c  = k / 9;
                        const int r  = k - c * 9;
                        const int ih = oh + r / 3 - 1;
                        const int iw = ow + (r % 3) - 1;
                        v[u] = ((unsigned)ih < (unsigned)H && (unsigned)iw < (unsigned)W)
                             ? fimg64[((size_t)c * H + ih) * W + iw] : 0ull;
                    }
                    pack_store8(dsm + 3 * CTILE, cvt_off + q * 16, v);
                }
            } else if (ch == 0) {
#pragma unroll
                for (int q = 0; q < 4; ++q) zero_store8(dsm + 3 * CTILE, cvt_off + q * 16);
            }
        }
        __syncthreads();

        // ---- MMA phase: 6 split-product pairs, grouped by A component ----
#pragma unroll
        for (int g = 0; g < 3; ++g) {
            const uint32_t tAg = sb + g * CTILE;
            const int nbj = (g == 0) ? 3 : ((g == 1) ? 2 : 1);
#pragma unroll
            for (int sk = 0; sk < 2; ++sk) {
                uint32_t av[4][4];
#pragma unroll
                for (int mf = 0; mf < 4; ++mf)
                    ldsm4(av[mf], tAg + a_off + mf * 16 * PITCH + sk * 32);
#pragma unroll
                for (int bj = 0; bj < 3; ++bj) {
                    if (bj >= nbj) break;
                    const uint32_t tBg = sb + (3 + bj) * CTILE;
                    uint32_t bv[2][4];
                    ldsm4(bv[0], tBg + b_off + sk * 32);
                    ldsm4(bv[1], tBg + b_off + 16 * PITCH + sk * 32);
#pragma unroll
                    for (int mf = 0; mf < 4; ++mf)
#pragma unroll
                        for (int nf = 0; nf < 4; ++nf)
                            mma16816(acc[mf][nf], av[mf], &bv[nf >> 1][(nf & 1) * 2]);
                }
            }
        }
        __syncthreads();

        // ---- cascade flush every 12 chunks (384 k-values) ----
        if (++fcnt == 12) {
            fcnt = 0;
#pragma unroll
            for (int i = 0; i < 4; ++i)
#pragma unroll
                for (int j = 0; j < 4; ++j)
#pragma unroll
                    for (int u = 0; u < 4; ++u) {
                        hi[i][j][u] += acc[i][j][u];
                        acc[i][j][u] = 0.f;
                    }
        }
    }

    // ---- epilogue: bias add + scatter (from hi; acc drained: nch % 12 == 0)
#pragma unroll
    for (int mf = 0; mf < 4; ++mf) {
        const int rb_ = m0 + m0w + mf * 16 + (lane >> 2);
#pragma unroll
        for (int half = 0; half < 2; ++half) {
            const int m = rb_ + half * 8;
            if (m >= M) continue;
            const float bias = (m < Mc) ? cb[m] : rb[m - Mc];
#pragma unroll
            for (int nf = 0; nf < 4; ++nf) {
#pragma unroll
                for (int e = 0; e < 2; ++e) {
                    const int cc = n0 + n0w + nf * 8 + (lane & 3) * 2 + e;
                    if (cc >= Ncols) continue;
                    const float v = hi[mf][nf][half * 2 + e] + bias;
                    const int im = cc / HW;
                    const int r  = cc % HW;
                    const int o_h = r / W, o_w = r - o_h * W;
                    const int base = (o_h * W + o_w) * an;
                    if (m < Mc) {
                        const int a = m / 81, t = m - a * 81;
                        const int anc = aoff + base + a;
                        g_cls[((size_t)im * NANCH + anc) * 81 + t] = v;
                    } else {
                        const int mm = m - Mc;
                        const int a = mm >> 2, t = mm & 3;
                        const int anc = aoff + base + a;
                        g_reg[((size_t)im * NANCH + anc) * 4 + t] = v;
                    }
                }
            }
        }
    }
}

// ---------------- softmax over 81 classes, drop background, threshold ----
// fused histogram; sum in fp64 (rounded once).
__global__ void softmax_kernel()
{
    const int w    = (blockIdx.x * blockDim.x + threadIdx.x) >> 5;
    const int lane = threadIdx.x & 31;
    if (w >= NIMG * NANCH) return;
    const int img  = w / NANCH;
    const float* in = g_cls + (size_t)w * 81;
    unsigned int* h = g_hist + img * 65536;

    const float NEG = -3.0e38f;
    float v0 = in[lane];
    float v1 = (lane + 32 < 81) ? in[lane + 32] : NEG;
    float v2 = (lane + 64 < 81) ? in[lane + 64] : NEG;
    float m = fmaxf(v0, fmaxf(v1, v2));
#pragma unroll
    for (int off = 16; off > 0; off >>= 1)
        m = fmaxf(m, __shfl_xor_sync(0xFFFFFFFFu, m, off));
    float e0 = expf(v0 - m);
    float e1 = (lane + 32 < 81) ? expf(v1 - m) : 0.f;
    float e2 = (lane + 64 < 81) ? expf(v2 - m) : 0.f;
    double s = (double)e0 + (double)e1 + (double)e2;
#pragma unroll
    for (int off = 16; off > 0; off >>= 1)
        s += __shfl_xor_sync(0xFFFFFFFFu, s, off);
    const float sf = (float)s;

    float* out = g_scr + (size_t)w * NCLS;
    if (lane >= 1) {
        float p = e0 / sf;
        const bool pos = (p > 0.01f);
        out[lane - 1] = pos ? p : 0.f;
        if (pos) atomicAdd(&h[__float_as_uint(p) >> 16], 1u);
    }
    if (lane + 32 < 81) {
        float p = e1 / sf;
        const bool pos = (p > 0.01f);
        out[lane + 31] = pos ? p : 0.f;
        if (pos) atomicAdd(&h[__float_as_uint(p) >> 16], 1u);
    }
    if (lane + 64 < 81) {
        float p = e2 / sf;
        const bool pos = (p > 0.01f);
        out[lane + 63] = pos ? p : 0.f;
        if (pos) atomicAdd(&h[__float_as_uint(p) >> 16], 1u);
    }
}

// ---------------- find boundary bucket (suffix count >= 400) ----------------
__global__ void boundary_kernel()
{
    __shared__ unsigned int cs[256];
    const int img = blockIdx.x, t = threadIdx.x;
    const unsigned int* h = g_hist + img * 65536;
    unsigned int s = 0;
    const int base = t * 256;
    for (int b = 0; b < 256; ++b) s += h[base + b];
    cs[t] = s;
    __syncthreads();
    if (t == 0) {
        unsigned int acc = 0, thr = 0;
        int chunk = -1;
        for (int c = 255; c >= 0; --c) {
            if (acc + cs[c] >= NCAND) { chunk = c; break; }
            acc += cs[c];
        }
        if (chunk >= 0) {
            for (int b = chunk * 256 + 255; b >= chunk * 256; --b) {
                acc += h[b];
                if (acc >= NCAND) { thr = (unsigned)b; break; }
            }
        }
        g_thr[img] = thr;
        g_cnt[img] = 0;
    }
}

// ---------------- collect top-400 superset ----------------
__global__ void collect_kernel()
{
    const int img = blockIdx.y;
    const unsigned int thr = g_thr[img];
    const float* f = g_scr + (size_t)img * FLATC;
    for (int j = blockIdx.x * blockDim.x + threadIdx.x; j < FLATC;
         j += gridDim.x * blockDim.x) {
        const float v = f[j];
        if (v > 0.f && (__float_as_uint(v) >> 16) >= thr) {
            const int p = atomicAdd(&g_cnt[img], 1);
            if (p < CAP) {
                g_cand_v[img * CAP + p] = v;
                g_cand_i[img * CAP + p] = j;
            }
        }
    }
}

// ---------------- bitonic sort (desc by value, asc by index on ties) ------
__global__ void __launch_bounds__(512) sort_kernel()
{
    __shared__ unsigned long long keys[CAP];
    const int img = blockIdx.x, tid = threadIdx.x;
    int n = g_cnt[img];
    if (n > CAP) n = CAP;

    for (int i = tid; i < CAP; i += 512) {
        unsigned long long key = 0ull;
        if (i < n) {
            const unsigned vb = __float_as_uint(g_cand_v[img * CAP + i]);
            const unsigned ix = (unsigned)g_cand_i[img * CAP + i];
            key = ((unsigned long long)vb << 32) | (0xFFFFFFFFu - ix);
        }
        keys[i] = key;
    }
    __syncthreads();

    for (int k = 2; k <= CAP; k <<= 1) {
        for (int j = k >> 1; j > 0; j >>= 1) {
            for (int i = tid; i < CAP; i += 512) {
                const int ixj = i ^ j;
                if (ixj > i) {
                    const bool desc = ((i & k) == 0);
                    const unsigned long long a = keys[i], bb = keys[ixj];
                    if (desc ? (a < bb) : (a > bb)) { keys[i] = bb; keys[ixj] = a; }
                }
            }
            __syncthreads();
        }
    }

    if (tid < NCAND) {
        const unsigned long long key = keys[tid];
        g_top_v[img * NCAND + tid] = __uint_as_float((unsigned)(key >> 32));
        g_top_i[img * NCAND + tid] = (int)(0xFFFFFFFFu - (unsigned)(key & 0xFFFFFFFFull));
    }
    __syncthreads();
    // padding path: fewer than 400 positives -> lax.top_k fills with the
    // lowest-index zero entries
    if (tid == 0 && n < NCAND) {
        const float* f = g_scr + (size_t)img * FLATC;
        int p = n;
        for (int j = 0; j < FLATC && p < NCAND; ++j) {
            if (f[j] == 0.0f) {
                g_top_v[img * NCAND + p] = 0.f;
                g_top_i[img * NCAND + p] = j;
                ++p;
            }
        }
    }
}

// ---------------- decode + class-aware NMS + final top-200 ----------------
__global__ void __launch_bounds__(512)
postnms_kernel(const float* __restrict__ priors, float* __restrict__ out)
{
    __shared__ float sx1[NCAND], sy1[NCAND], sx2[NCAND], sy2[NCAND];
    __shared__ float ox1[NCAND], oy1[NCAND], ox2[NCAND], oy2[NCAND], oar[NCAND];
    __shared__ float s_sc[NCAND];
    __shared__ int   s_cls[NCAND], s_keep[NCAND];
    __shared__ int   s_fi[NOUT];

    const int img = blockIdx.x, tid = threadIdx.x;

    if (tid < NCAND) {
        const float v  = g_top_v[img * NCAND + tid];
        const int idx  = g_top_i[img * NCAND + tid];
        const int cls  = idx % NCLS + 1;
        const int anc  = idx / NCLS;
        const float* d = g_reg + ((size_t)img * NANCH + anc) * 4;
        const float* p = priors + (size_t)anc * 4;
        const float cx = p[0] + d[0] * 0.1f * p[2];
        const float cy = p[1] + d[1] * 0.1f * p[3];
        const float w  = p[2] * expf(fminf(d[2] * 0.2f, CLIPV));
        const float h  = p[3] * expf(fminf(d[3] * 0.2f, CLIPV));
        float x1 = cx - 0.5f * w, y1 = cy - 0.5f * h;
        float x2 = cx + 0.5f * w, y2 = cy + 0.5f * h;
        x1 = fminf(fmaxf(x1, 0.f), 300.f);
        y1 = fminf(fmaxf(y1, 0.f), 300.f);
        x2 = fminf(fmaxf(x2, 0.f), 300.f);
        y2 = fminf(fmaxf(y2, 0.f), 300.f);
        const bool valid = (v > 0.f) && (x2 > x1) && (y2 > y1);
        sx1[tid] = x1; sy1[tid] = y1; sx2[tid] = x2; sy2[tid] = y2;
        s_sc[tid] = valid ? v : 0.f;
        s_cls[tid] = cls;
        s_keep[tid] = valid ? 1 : 0;
        // class offset applied BEFORE area/IoU, exactly as in the reference
        const float off = (float)cls * 301.0f;
        const float a1 = x1 + off, b1 = y1 + off, a2 = x2 + off, b2 = y2 + off;
        ox1[tid] = a1; oy1[tid] = b1; ox2[tid] = a2; oy2[tid] = b2;
        oar[tid] = (a2 - a1) * (b2 - b1);
    }
    __syncthreads();

    // greedy NMS, iteration order identical to the fori_loop
    for (int i = 0; i < NCAND; ++i) {
        if (s_keep[i]) {
            const int j = tid;
            if (j > i && j < NCAND && s_keep[j]) {
                const float ltx = fmaxf(ox1[i], ox1[j]);
                const float lty = fmaxf(oy1[i], oy1[j]);
                const float rbx = fminf(ox2[i], ox2[j]);
                const float rby = fminf(oy2[i], oy2[j]);
                const float ww = fmaxf(rbx - ltx, 0.f);
                const float hh = fmaxf(rby - lty, 0.f);
                const float inter = ww * hh;
                const float iou = inter / (oar[i] + oar[j] - inter + 1e-9f);
                if (iou > 0.45f) s_keep[j] = 0;
            }
        }
        __syncthreads();
    }

    // final top_k(where(keep, s, 0), 200):
    // kept positions ascending (s is already sorted desc), then zero-valued
    // (non-kept) positions ascending -- matches value-desc/index-asc ties.
    if (tid == 0) {
        int p = 0;
        for (int i = 0; i < NCAND && p < NOUT; ++i) if (s_keep[i])  s_fi[p++] = i;
        for (int i = 0; i < NCAND && p < NOUT; ++i) if (!s_keep[i]) s_fi[p++] = i;
    }
    __syncthreads();

    if (tid < NOUT) {
        const int o = s_fi[tid];
        const float fsv = s_keep[o] ? s_sc[o] : 0.f;
        const size_t bo = ((size_t)img * NOUT + tid) * 4;
        out[bo + 0] = sx1[o];
        out[bo + 1] = sy1[o];
        out[bo + 2] = sx2[o];
        out[bo + 3] = sy2[o];
        out[(size_t)NIMG * NOUT * 4 + img * NOUT + tid] = fsv;
        out[(size_t)NIMG * NOUT * 5 + img * NOUT + tid] =
            (fsv > 0.f) ? (float)s_cls[o] : 0.f;
    }
}

// ---------------- host launch ----------------
extern "C" void kernel_launch(void* const* d_in, const int* in_sizes, int n_in,
                              void* d_out, int out_size)
{
    (void)out_size;
    // input-order detection: signature order has feat1 (5,914,624 elems) at
    // slot 1; dict-insertion order has cls_w0 (1,492,992) there.
    const bool sig = (n_in > 1 && in_sizes[1] == 16 * 1024 * 19 * 19);
    int fI[6], cwI[6], cbI[6], rwI[6], rbI[6];
    for (int i = 0; i < 6; ++i) {
        if (sig) {
            fI[i] = i;
            cwI[i] = 6 + 2 * i;  cbI[i] = 7 + 2 * i;
            rwI[i] = 18 + 2 * i; rbI[i] = 19 + 2 * i;
        } else {
            fI[i] = 5 * i;
            cwI[i] = 5 * i + 1; cbI[i] = 5 * i + 2;
            rwI[i] = 5 * i + 3; rbI[i] = 5 * i + 4;
        }
    }
    const float* priors = (const float*)d_in[30];
    float* out = (float*)d_out;

    HeadPtrs P;
    for (int i = 0; i < 6; ++i) {
        P.feat[i] = (const float*)d_in[fI[i]];
        P.cw[i]   = (const float*)d_in[cwI[i]];
        P.cb[i]   = (const float*)d_in[cbI[i]];
        P.rw[i]   = (const float*)d_in[rwI[i]];
        P.rb[i]   = (const float*)d_in[rbI[i]];
    }

    static bool attr_set = false;
    if (!attr_set) {
        cudaFuncSetAttribute(head_gemm_hmma,
                             cudaFuncAttributeMaxDynamicSharedMemorySize,
                             SMEM_HM);
        attr_set = true;
    }

    zero_kernel<<<512, 256>>>();
    presplit_w<<<1024, 256>>>(P);
    presplit_f<<<1024, 256>>>(P);

    // single merged launch: 184(L1) + 543(L0) + 52(L2) + 16(L3) + 6(L4) + 3(L5)
    head_gemm_hmma<<<804, 256, SMEM_HM>>>(P);

    softmax_kernel<<<(NIMG * NANCH + 7) / 8, 256>>>();   // hist fused in
    boundary_kernel<<<NIMG, 256>>>();
    collect_kernel<<<dim3(256, NIMG), 256>>>();
    sort_kernel<<<NIMG, 512>>>();
    postnms_kernel<<<NIMG, 512>>>(priors, out);
}

// round 17
// speedup vs baseline: 1.1653x; 1.1653x over previous
#include <cuda_runtime.h>
#include <cuda_bf16.h>
#include <math.h>
#include <stdint.h>

#define NIMG   16
#define NANCH  8732
#define NCLS   80
#define FLATC  (NANCH * NCLS)     // 698560
#define NCAND  400
#define NOUT   200
#define CAP    4096
#define CLIPV  4.135166556742356f // log(1000/16)

// ---------------- device scratch (no allocations allowed) ----------------
__device__ float        g_cls[(size_t)NIMG * NANCH * 81];   // logits
__device__ float        g_scr[(size_t)NIMG * FLATC];        // thresholded softmax scores
__device__ float        g_reg[(size_t)NIMG * NANCH * 4];    // box deltas
__device__ unsigned int g_hist[NIMG * 65536];
__device__ int          g_cnt[NIMG];
__device__ unsigned int g_thr[NIMG];
__device__ float        g_cand_v[NIMG * CAP];
__device__ int          g_cand_i[NIMG * CAP];
__device__ float        g_top_v[NIMG * NCAND];
__device__ int          g_top_i[NIMG * NCAND];

// ---------------- zero histograms ----------------
__global__ void zero_kernel()
{
    int i  = blockIdx.x * blockDim.x + threadIdx.x;
    int st = gridDim.x * blockDim.x;
    for (int t = i; t < NIMG * 65536; t += st) g_hist[t] = 0u;
}

// ============ conv heads via warp-level HMMA (bf16 3-way split) ============
// Round-15 structure (in-loop split; best passing) + DOUBLE-BUFFERED smem
// component tiles: iteration ch converts chunk ch+1 into stage (ch+1)&1 and
// MMAs chunk ch from stage ch&1, ONE barrier per chunk -> conversion (fma/alu)
// and MMA (tensor/ldsm) streams share each inter-barrier window and fill each
// other's stalls. Same split ops + same MMA order -> bitwise-identical output.
struct HeadPtrs {
    const float* feat[6];
    const float* cw[6];
    const float* cb[6];
    const float* rw[6];
    const float* rb[6];
};

__device__ __constant__ int d_C[6]    = {512, 1024, 512, 256, 256, 256};
__device__ __constant__ int d_H[6]    = {38, 19, 10, 5, 3, 1};
__device__ __constant__ int d_AN[6]   = {4, 6, 6, 6, 4, 4};
__device__ __constant__ int d_AOFF[6] = {0, 5776, 7942, 8542, 8692, 8728};
__device__ __constant__ int d_NX[6]   = {181, 46, 13, 4, 2, 1};  // ceil(Nc/128)

#define PITCH   80                   // 64B data + 16B pad: conflict-free ldmatrix
#define CTILE   (128 * PITCH)        // one component tile: 10240 B
#define STAGE   (6 * CTILE)          // 6 comp tiles per stage: 61440 B
#define SMEM_HM (2 * STAGE)          // 122880 B double-buffered

__device__ __forceinline__ uint32_t bfpack(float x, float y)
{
    const __nv_bfloat16 hx = __float2bfloat16(x);
    const __nv_bfloat16 hy = __float2bfloat16(y);
    return (uint32_t)__bfloat16_as_ushort(hx) |
           ((uint32_t)__bfloat16_as_ushort(hy) << 16);
}

// split 8 consecutive values into 3 bf16 components; store 16B per comp tile
__device__ __forceinline__ void split_store8(char* base, uint32_t off, const float* v)
{
    uint32_t p0[4], p1[4], p2[4];
#pragma unroll
    for (int u = 0; u < 4; ++u) {
        const float x = v[2 * u], y = v[2 * u + 1];
        const __nv_bfloat16 hx = __float2bfloat16(x);
        const __nv_bfloat16 hy = __float2bfloat16(y);
        const float rx = x - __bfloat162float(hx);
        const float ry = y - __bfloat162float(hy);
        p0[u] = (uint32_t)__bfloat16_as_ushort(hx) |
                ((uint32_t)__bfloat16_as_ushort(hy) << 16);
        const __nv_bfloat16 gx = __float2bfloat16(rx);
        const __nv_bfloat16 gy = __float2bfloat16(ry);
        const float sx = rx - __bfloat162float(gx);
        const float sy = ry - __bfloat162float(gy);
        p1[u] = (uint32_t)__bfloat16_as_ushort(gx) |
                ((uint32_t)__bfloat16_as_ushort(gy) << 16);
        p2[u] = bfpack(sx, sy);
    }
    *(uint4*)(base + off)              = make_uint4(p0[0], p0[1], p0[2], p0[3]);
    *(uint4*)(base + CTILE + off)      = make_uint4(p1[0], p1[1], p1[2], p1[3]);
    *(uint4*)(base + 2 * CTILE + off)  = make_uint4(p2[0], p2[1], p2[2], p2[3]);
}

__device__ __forceinline__ void zero_store8(char* base, uint32_t off)
{
    const uint4 z = make_uint4(0, 0, 0, 0);
    *(uint4*)(base + off)             = z;
    *(uint4*)(base + CTILE + off)     = z;
    *(uint4*)(base + 2 * CTILE + off) = z;
}

__device__ __forceinline__ void ldsm4(uint32_t* r, uint32_t addr)
{
    asm volatile("ldmatrix.sync.aligned.m8n8.x4.shared.b16 {%0,%1,%2,%3}, [%4];"
                 : "=r"(r[0]), "=r"(r[1]), "=r"(r[2]), "=r"(r[3]) : "r"(addr));
}

__device__ __forceinline__ void mma16816(float* c, const uint32_t* a, const uint32_t* b)
{
    asm volatile(
        "mma.sync.aligned.m16n8k16.row.col.f32.bf16.bf16.f32 "
        "{%0,%1,%2,%3},{%4,%5,%6,%7},{%8,%9},{%0,%1,%2,%3};"
        : "+f"(c[0]), "+f"(c[1]), "+f"(c[2]), "+f"(c[3])
        : "r"(a[0]), "r"(a[1]), "r"(a[2]), "r"(a[3]), "r"(b[0]), "r"(b[1]));
}

__global__ void __launch_bounds__(256, 1)
head_gemm_hmma(const HeadPtrs P)
{
    // ---- block -> (level, tile) mapping; work-heavy levels first ----
    const int b = blockIdx.x;
    int li, rel;
    if      (b < 184) { li = 1; rel = b; }
    else if (b < 727) { li = 0; rel = b - 184; }
    else if (b < 779) { li = 2; rel = b - 727; }
    else if (b < 795) { li = 3; rel = b - 779; }
    else if (b < 801) { li = 4; rel = b - 795; }
    else              { li = 5; rel = b - 801; }

    const int C  = d_C[li];
    const int H  = d_H[li];
    const int W  = H;
    const int an = d_AN[li];
    const int aoff = d_AOFF[li];
    const int nx = d_NX[li];
    const int Mc = an * 81;
    const int M  = an * 85;
    const int HW = H * W;
    const int Ncols = NIMG * HW;
    const int K  = C * 9;            // 4608 / 9216 / 2304: all % 384 == 0

    const float* __restrict__ feat = P.feat[li];
    const float* __restrict__ cw   = P.cw[li];
    const float* __restrict__ cb   = P.cb[li];
    const float* __restrict__ rw   = P.rw[li];
    const float* __restrict__ rb   = P.rb[li];

    extern __shared__ __align__(16) char dsm[];
    uint32_t sb;
    asm("{ .reg .u64 t; cvta.to.shared.u64 t, %1; cvt.u32.u64 %0, t; }"
        : "=r"(sb) : "l"(dsm));

    const int tid  = threadIdx.x;
    const int wid  = tid >> 5, lane = tid & 31;
    const int m0   = (rel / nx) * 128;
    const int n0   = (rel % nx) * 128;

    // ---- converter role: threads 0-127 -> A rows, 128-255 -> B cols ----
    const bool isA = (tid < 128);
    const int crow = isA ? tid : tid - 128;

    const float* arow = nullptr;
    if (isA) {
        const int am = m0 + crow;
        if (am < Mc)      arow = cw + (size_t)am * K;
        else if (am < M)  arow = rw + (size_t)(am - Mc) * K;
    }
    bool colv = false;
    int img = 0, oh = 0, ow = 0;
    if (!isA) {
        const int col = n0 + crow;
        colv = (col < Ncols);
        if (colv) { img = col / HW; int r = col % HW; oh = r / W; ow = r % W; }
    }
    const float* fimg = feat + (size_t)img * C * HW;
    const uint32_t cvt_off = (uint32_t)crow * PITCH;

    // conversion of chunk cc into stage st (invalid rows zeroed for cc < 2,
    // covering both stages once)
    auto convert_chunk = [&](int cc, int st) {
        char* stA = dsm + st * STAGE;
        char* stB = stA + 3 * CTILE;
        const int k0 = cc << 5;
        if (isA) {
            if (arow) {
#pragma unroll
                for (int q = 0; q < 4; ++q) {
                    const float4 v0 = *(const float4*)(arow + k0 + q * 8);
                    const float4 v1 = *(const float4*)(arow + k0 + q * 8 + 4);
                    float va[8] = { v0.x, v0.y, v0.z, v0.w, v1.x, v1.y, v1.z, v1.w };
                    split_store8(stA, cvt_off + q * 16, va);
                }
            } else if (cc < 2) {
#pragma unroll
                for (int q = 0; q < 4; ++q) zero_store8(stA, cvt_off + q * 16);
            }
        } else {
            if (colv) {
#pragma unroll
                for (int q = 0; q < 4; ++q) {
                    float vb[8];
#pragma unroll
                    for (int u = 0; u < 8; ++u) {
                        const int k = k0 + q * 8 + u;
                        float v = 0.f;
                        const int c  = k / 9;
                        const int r  = k - c * 9;
                        const int ih = oh + r / 3 - 1;
                        const int iw = ow + (r % 3) - 1;
                        if ((unsigned)ih < (unsigned)H && (unsigned)iw < (unsigned)W)
                            v = fimg[((size_t)c * H + ih) * W + iw];
                        vb[u] = v;
                    }
                    split_store8(stB, cvt_off + q * 16, vb);
                }
            } else if (cc < 2) {
#pragma unroll
                for (int q = 0; q < 4; ++q) zero_store8(stB, cvt_off + q * 16);
            }
        }
    };

    // ---- warp tile mapping: 8 warps = 2 m-halves x 4 n-quarters ----
    const int m0w = (wid >> 2) * 64;   // 0 or 64
    const int n0w = (wid & 3) * 32;    // 0,32,64,96

    const uint32_t a_off = (uint32_t)(m0w + (lane & 15)) * PITCH + (lane >> 4) * 16;
    const uint32_t b_off = (uint32_t)(n0w + (lane & 7) + ((lane >> 4) << 3)) * PITCH
                         + ((lane >> 3) & 1) * 16;

    float acc[4][4][4], hi[4][4][4];
#pragma unroll
    for (int i = 0; i < 4; ++i)
#pragma unroll
        for (int j = 0; j < 4; ++j)
#pragma unroll
            for (int u = 0; u < 4; ++u) { acc[i][j][u] = 0.f; hi[i][j][u] = 0.f; }

    const int nch = K >> 5;          // K-chunks of 32
    int fcnt = 0;

    // ---- prologue: convert chunk 0 into stage 0 ----
    convert_chunk(0, 0);
    __syncthreads();

    for (int ch = 0; ch < nch; ++ch) {
        // ---- convert chunk ch+1 into the other stage (overlaps with MMA) --
        if (ch + 1 < nch) convert_chunk(ch + 1, (ch + 1) & 1);

        // ---- MMA phase on chunk ch from stage ch&1 ----
        const uint32_t stg = sb + (uint32_t)(ch & 1) * STAGE;
#pragma unroll
        for (int g = 0; g < 3; ++g) {
            const uint32_t tAg = stg + g * CTILE;
            const int nbj = (g == 0) ? 3 : ((g == 1) ? 2 : 1);
#pragma unroll
            for (int sk = 0; sk < 2; ++sk) {
                uint32_t av[4][4];
#pragma unroll
                for (int mf = 0; mf < 4; ++mf)
                    ldsm4(av[mf], tAg + a_off + mf * 16 * PITCH + sk * 32);
#pragma unroll
                for (int bj = 0; bj < 3; ++bj) {
                    if (bj >= nbj) break;
                    const uint32_t tBg = stg + (3 + bj) * CTILE;
                    uint32_t bv[2][4];
                    ldsm4(bv[0], tBg + b_off + sk * 32);
                    ldsm4(bv[1], tBg + b_off + 16 * PITCH + sk * 32);
#pragma unroll
                    for (int mf = 0; mf < 4; ++mf)
#pragma unroll
                        for (int nf = 0; nf < 4; ++nf)
                            mma16816(acc[mf][nf], av[mf], &bv[nf >> 1][(nf & 1) * 2]);
                }
            }
        }

        // ---- cascade flush every 12 chunks (384 k-values) ----
        if (++fcnt == 12) {
            fcnt = 0;
#pragma unroll
            for (int i = 0; i < 4; ++i)
#pragma unroll
                for (int j = 0; j < 4; ++j)
#pragma unroll
                    for (int u = 0; u < 4; ++u) {
                        hi[i][j][u] += acc[i][j][u];
                        acc[i][j][u] = 0.f;
                    }
        }

        // single barrier: publishes chunk ch+1 stores AND orders this
        // iteration's MMA reads of stage ch&1 before its overwrite at ch+1
        __syncthreads();
    }

    // ---- epilogue: bias add + scatter (from hi; acc drained: nch % 12 == 0)
#pragma unroll
    for (int mf = 0; mf < 4; ++mf) {
        const int rb_ = m0 + m0w + mf * 16 + (lane >> 2);
#pragma unroll
        for (int half = 0; half < 2; ++half) {
            const int m = rb_ + half * 8;
            if (m >= M) continue;
            const float bias = (m < Mc) ? cb[m] : rb[m - Mc];
#pragma unroll
            for (int nf = 0; nf < 4; ++nf) {
#pragma unroll
                for (int e = 0; e < 2; ++e) {
                    const int cc = n0 + n0w + nf * 8 + (lane & 3) * 2 + e;
                    if (cc >= Ncols) continue;
                    const float v = hi[mf][nf][half * 2 + e] + bias;
                    const int im = cc / HW;
                    const int r  = cc % HW;
                    const int o_h = r / W, o_w = r - o_h * W;
                    const int base = (o_h * W + o_w) * an;
                    if (m < Mc) {
                        const int a = m / 81, t = m - a * 81;
                        const int anc = aoff + base + a;
                        g_cls[((size_t)im * NANCH + anc) * 81 + t] = v;
                    } else {
                        const int mm = m - Mc;
                        const int a = mm >> 2, t = mm & 3;
                        const int anc = aoff + base + a;
                        g_reg[((size_t)im * NANCH + anc) * 4 + t] = v;
                    }
                }
            }
        }
    }
}

// ---------------- softmax over 81 classes, drop background, threshold ----
// fused histogram; sum in fp64 (rounded once).
__global__ void softmax_kernel()
{
    const int w    = (blockIdx.x * blockDim.x + threadIdx.x) >> 5;
    const int lane = threadIdx.x & 31;
    if (w >= NIMG * NANCH) return;
    const int img  = w / NANCH;
    const float* in = g_cls + (size_t)w * 81;
    unsigned int* h = g_hist + img * 65536;

    const float NEG = -3.0e38f;
    float v0 = in[lane];
    float v1 = (lane + 32 < 81) ? in[lane + 32] : NEG;
    float v2 = (lane + 64 < 81) ? in[lane + 64] : NEG;
    float m = fmaxf(v0, fmaxf(v1, v2));
#pragma unroll
    for (int off = 16; off > 0; off >>= 1)
        m = fmaxf(m, __shfl_xor_sync(0xFFFFFFFFu, m, off));
    float e0 = expf(v0 - m);
    float e1 = (lane + 32 < 81) ? expf(v1 - m) : 0.f;
    float e2 = (lane + 64 < 81) ? expf(v2 - m) : 0.f;
    double s = (double)e0 + (double)e1 + (double)e2;
#pragma unroll
    for (int off = 16; off > 0; off >>= 1)
        s += __shfl_xor_sync(0xFFFFFFFFu, s, off);
    const float sf = (float)s;

    float* out = g_scr + (size_t)w * NCLS;
    if (lane >= 1) {
        float p = e0 / sf;
        const bool pos = (p > 0.01f);
        out[lane - 1] = pos ? p : 0.f;
        if (pos) atomicAdd(&h[__float_as_uint(p) >> 16], 1u);
    }
    if (lane + 32 < 81) {
        float p = e1 / sf;
        const bool pos = (p > 0.01f);
        out[lane + 31] = pos ? p : 0.f;
        if (pos) atomicAdd(&h[__float_as_uint(p) >> 16], 1u);
    }
    if (lane + 64 < 81) {
        float p = e2 / sf;
        const bool pos = (p > 0.01f);
        out[lane + 63] = pos ? p : 0.f;
        if (pos) atomicAdd(&h[__float_as_uint(p) >> 16], 1u);
    }
}

// ---------------- find boundary bucket (suffix count >= 400) ----------------
__global__ void boundary_kernel()
{
    __shared__ unsigned int cs[256];
    const int img = blockIdx.x, t = threadIdx.x;
    const unsigned int* h = g_hist + img * 65536;
    unsigned int s = 0;
    const int base = t * 256;
    for (int b = 0; b < 256; ++b) s += h[base + b];
    cs[t] = s;
    __syncthreads();
    if (t == 0) {
        unsigned int acc = 0, thr = 0;
        int chunk = -1;
        for (int c = 255; c >= 0; --c) {
            if (acc + cs[c] >= NCAND) { chunk = c; break; }
            acc += cs[c];
        }
        if (chunk >= 0) {
            for (int b = chunk * 256 + 255; b >= chunk * 256; --b) {
                acc += h[b];
                if (acc >= NCAND) { thr = (unsigned)b; break; }
            }
        }
        g_thr[img] = thr;
        g_cnt[img] = 0;
    }
}

// ---------------- collect top-400 superset ----------------
__global__ void collect_kernel()
{
    const int img = blockIdx.y;
    const unsigned int thr = g_thr[img];
    const float* f = g_scr + (size_t)img * FLATC;
    for (int j = blockIdx.x * blockDim.x + threadIdx.x; j < FLATC;
         j += gridDim.x * blockDim.x) {
        const float v = f[j];
        if (v > 0.f && (__float_as_uint(v) >> 16) >= thr) {
            const int p = atomicAdd(&g_cnt[img], 1);
            if (p < CAP) {
                g_cand_v[img * CAP + p] = v;
                g_cand_i[img * CAP + p] = j;
            }
        }
    }
}

// ---------------- bitonic sort (desc by value, asc by index on ties) ------
__global__ void __launch_bounds__(512) sort_kernel()
{
    __shared__ unsigned long long keys[CAP];
    const int img = blockIdx.x, tid = threadIdx.x;
    int n = g_cnt[img];
    if (n > CAP) n = CAP;

    for (int i = tid; i < CAP; i += 512) {
        unsigned long long key = 0ull;
        if (i < n) {
            const unsigned vb = __float_as_uint(g_cand_v[img * CAP + i]);
            const unsigned ix = (unsigned)g_cand_i[img * CAP + i];
            key = ((unsigned long long)vb << 32) | (0xFFFFFFFFu - ix);
        }
        keys[i] = key;
    }
    __syncthreads();

    for (int k = 2; k <= CAP; k <<= 1) {
        for (int j = k >> 1; j > 0; j >>= 1) {
            for (int i = tid; i < CAP; i += 512) {
                const int ixj = i ^ j;
                if (ixj > i) {
                    const bool desc = ((i & k) == 0);
                    const unsigned long long a = keys[i], bb = keys[ixj];
                    if (desc ? (a < bb) : (a > bb)) { keys[i] = bb; keys[ixj] = a; }
                }
            }
            __syncthreads();
        }
    }

    if (tid < NCAND) {
        const unsigned long long key = keys[tid];
        g_top_v[img * NCAND + tid] = __uint_as_float((unsigned)(key >> 32));
        g_top_i[img * NCAND + tid] = (int)(0xFFFFFFFFu - (unsigned)(key & 0xFFFFFFFFull));
    }
    __syncthreads();
    // padding path: fewer than 400 positives -> lax.top_k fills with the
    // lowest-index zero entries
    if (tid == 0 && n < NCAND) {
        const float* f = g_scr + (size_t)img * FLATC;
        int p = n;
        for (int j = 0; j < FLATC && p < NCAND; ++j) {
            if (f[j] == 0.0f) {
                g_top_v[img * NCAND + p] = 0.f;
                g_top_i[img * NCAND + p] = j;
                ++p;
            }
        }
    }
}

// ---------------- decode + class-aware NMS + final top-200 ----------------
__global__ void __launch_bounds__(512)
postnms_kernel(const float* __restrict__ priors, float* __restrict__ out)
{
    __shared__ float sx1[NCAND], sy1[NCAND], sx2[NCAND], sy2[NCAND];
    __shared__ float ox1[NCAND], oy1[NCAND], ox2[NCAND], oy2[NCAND], oar[NCAND];
    __shared__ float s_sc[NCAND];
    __shared__ int   s_cls[NCAND], s_keep[NCAND];
    __shared__ int   s_fi[NOUT];

    const int img = blockIdx.x, tid = threadIdx.x;

    if (tid < NCAND) {
        const float v  = g_top_v[img * NCAND + tid];
        const int idx  = g_top_i[img * NCAND + tid];
        const int cls  = idx % NCLS + 1;
        const int anc  = idx / NCLS;
        const float* d = g_reg + ((size_t)img * NANCH + anc) * 4;
        const float* p = priors + (size_t)anc * 4;
        const float cx = p[0] + d[0] * 0.1f * p[2];
        const float cy = p[1] + d[1] * 0.1f * p[3];
        const float w  = p[2] * expf(fminf(d[2] * 0.2f, CLIPV));
        const float h  = p[3] * expf(fminf(d[3] * 0.2f, CLIPV));
        float x1 = cx - 0.5f * w, y1 = cy - 0.5f * h;
        float x2 = cx + 0.5f * w, y2 = cy + 0.5f * h;
        x1 = fminf(fmaxf(x1, 0.f), 300.f);
        y1 = fminf(fmaxf(y1, 0.f), 300.f);
        x2 = fminf(fmaxf(x2, 0.f), 300.f);
        y2 = fminf(fmaxf(y2, 0.f), 300.f);
        const bool valid = (v > 0.f) && (x2 > x1) && (y2 > y1);
        sx1[tid] = x1; sy1[tid] = y1; sx2[tid] = x2; sy2[tid] = y2;
        s_sc[tid] = valid ? v : 0.f;
        s_cls[tid] = cls;
        s_keep[tid] = valid ? 1 : 0;
        // class offset applied BEFORE area/IoU, exactly as in the reference
        const float off = (float)cls * 301.0f;
        const float a1 = x1 + off, b1 = y1 + off, a2 = x2 + off, b2 = y2 + off;
        ox1[tid] = a1; oy1[tid] = b1; ox2[tid] = a2; oy2[tid] = b2;
        oar[tid] = (a2 - a1) * (b2 - b1);
    }
    __syncthreads();

    // greedy NMS, iteration order identical to the fori_loop
    for (int i = 0; i < NCAND; ++i) {
        if (s_keep[i]) {
            const int j = tid;
            if (j > i && j < NCAND && s_keep[j]) {
                const float ltx = fmaxf(ox1[i], ox1[j]);
                const float lty = fmaxf(oy1[i], oy1[j]);
                const float rbx = fminf(ox2[i], ox2[j]);
                const float rby = fminf(oy2[i], oy2[j]);
                const float ww = fmaxf(rbx - ltx, 0.f);
                const float hh = fmaxf(rby - lty, 0.f);
                const float inter = ww * hh;
                const float iou = inter / (oar[i] + oar[j] - inter + 1e-9f);
                if (iou > 0.45f) s_keep[j] = 0;
            }
        }
        __syncthreads();
    }

    // final top_k(where(keep, s, 0), 200):
    // kept positions ascending (s is already sorted desc), then zero-valued
    // (non-kept) positions ascending -- matches value-desc/index-asc ties.
    if (tid == 0) {
        int p = 0;
        for (int i = 0; i < NCAND && p < NOUT; ++i) if (s_keep[i])  s_fi[p++] = i;
        for (int i = 0; i < NCAND && p < NOUT; ++i) if (!s_keep[i]) s_fi[p++] = i;
    }
    __syncthreads();

    if (tid < NOUT) {
        const int o = s_fi[tid];
        const float fsv = s_keep[o] ? s_sc[o] : 0.f;
        const size_t bo = ((size_t)img * NOUT + tid) * 4;
        out[bo + 0] = sx1[o];
        out[bo + 1] = sy1[o];
        out[bo + 2] = sx2[o];
        out[bo + 3] = sy2[o];
        out[(size_t)NIMG * NOUT * 4 + img * NOUT + tid] = fsv;
        out[(size_t)NIMG * NOUT * 5 + img * NOUT + tid] =
            (fsv > 0.f) ? (float)s_cls[o] : 0.f;
    }
}

// ---------------- host launch ----------------
extern "C" void kernel_launch(void* const* d_in, const int* in_sizes, int n_in,
                              void* d_out, int out_size)
{
    (void)out_size;
    // input-order detection: signature order has feat1 (5,914,624 elems) at
    // slot 1; dict-insertion order has cls_w0 (1,492,992) there.
    const bool sig = (n_in > 1 && in_sizes[1] == 16 * 1024 * 19 * 19);
    int fI[6], cwI[6], cbI[6], rwI[6], rbI[6];
    for (int i = 0; i < 6; ++i) {
        if (sig) {
            fI[i] = i;
            cwI[i] = 6 + 2 * i;  cbI[i] = 7 + 2 * i;
            rwI[i] = 18 + 2 * i; rbI[i] = 19 + 2 * i;
        } else {
            fI[i] = 5 * i;
            cwI[i] = 5 * i + 1; cbI[i] = 5 * i + 2;
            rwI[i] = 5 * i + 3; rbI[i] = 5 * i + 4;
        }
    }
    const float* priors = (const float*)d_in[30];
    float* out = (float*)d_out;

    HeadPtrs P;
    for (int i = 0; i < 6; ++i) {
        P.feat[i] = (const float*)d_in[fI[i]];
        P.cw[i]   = (const float*)d_in[cwI[i]];
        P.cb[i]   = (const float*)d_in[cbI[i]];
        P.rw[i]   = (const float*)d_in[rwI[i]];
        P.rb[i]   = (const float*)d_in[rbI[i]];
    }

    static bool attr_set = false;
    if (!attr_set) {
        cudaFuncSetAttribute(head_gemm_hmma,
                             cudaFuncAttributeMaxDynamicSharedMemorySize,
                             SMEM_HM);
        attr_set = true;
    }

    zero_kernel<<<512, 256>>>();

    // single merged launch: 184(L1) + 543(L0) + 52(L2) + 16(L3) + 6(L4) + 3(L5)
    head_gemm_hmma<<<804, 256, SMEM_HM>>>(P);

    softmax_kernel<<<(NIMG * NANCH + 7) / 8, 256>>>();   // hist fused in
    boundary_kernel<<<NIMG, 256>>>();
    collect_kernel<<<dim3(256, NIMG), 256>>>();
    sort_kernel<<<NIMG, 512>>>();
    postnms_kernel<<<NIMG, 512>>>(priors, out);
}